// round 8
// baseline (speedup 1.0000x reference)
#include <cuda_runtime.h>
#include <math.h>
#include <stdint.h>

// ---------------------------------------------------------------------------
// QuantSoftmax: B=32, C=128, H=W=80 (HW=6400). int32 input (int8 repr, zp=0),
// float32 output. Piecewise-quantized exp (qint16) + reciprocal (qint16),
// requantized to int8*OUT_SCALE.
//
// exp collapses to a 256-entry LUT over d = qmax-q, built once per launch.
// Main kernel: thread = 4 consecutive pixels x 16 channels (int4/float4 I/O,
// 512B per warp access). Bytes of each packed word = 4 pixels, so per-pixel
// channel max falls out of __vmaxs4 and d = __vsub4. Exp LUT replicated 32x
// in smem (bank = lane) -> strictly conflict-free lookups; pass 3 re-looks-up
// instead of caching (regs stay ~40). 256-thread CTAs, 6/SM.
// ---------------------------------------------------------------------------

#define C_DIM 128
#define HW_DIM 6400
#define NTHREADS 256     // 8 warps = 8 channel-slices of 16; 128 px per CTA
#define PX_PER_CTA 128

__device__ float g_exp_lut[256];   // quantized exp value (integer-valued float)
__device__ float g_rtab1[256];     // recip table, region (0.1, 250)
__device__ float g_rtab2[256];     // recip table, region (250, 500)

__device__ __forceinline__ float quant_i16(float y, float scale) {
    float q = rintf(__fdiv_rn(y, scale));           // jnp.round = half-even
    return fminf(fmaxf(q, -32768.0f), 32767.0f);
}

__device__ __forceinline__ float exp_f32(float x) {
    return (float)exp((double)x);                   // ~correctly-rounded f32 exp
}

// one block, 256 threads: build LUTs
__global__ void build_luts_kernel(const float* __restrict__ ds_ptr) {
    int i = threadIdx.x;                            // 0..255
    float ds = ds_ptr[0];
    const float ESCALE = (float)(2.0 / 65535.0);
    const float RSCALE = (float)((1.0 / 0.1) * 2.0 / 65535.0);

    // ---- exp LUT over d = qmax - q in [0,255], x = -d*ds ----
    float x = __fmul_rn(-(float)i, ds);
    float y = quant_i16(exp_f32(-40.0f), ESCALE);   // left constant
    if (x >= -40.0f) {                              // line (-40,-20)
        float y0 = exp_f32(-40.0f), y1 = exp_f32(-20.0f);
        float t = __fadd_rn(y0, __fmul_rn(__fadd_rn(x, 40.0f),
                                          __fdiv_rn(__fadd_rn(y1, -y0), 20.0f)));
        y = quant_i16(t, ESCALE);
    }
    if (x >= -20.0f) {                              // table (-20,-10)
        float idxf = rintf(__fmul_rn(__fadd_rn(x, 20.0f), (float)(255.0 / 10.0)));
        idxf = fminf(fmaxf(idxf, 0.0f), 255.0f);
        float step = __fdiv_rn(10.0f, 255.0f);
        float xs = __fadd_rn(-20.0f, __fmul_rn(idxf, step));
        y = quant_i16(exp_f32(xs), ESCALE);
    }
    if (x >= -10.0f) {                              // table (-10,0)
        float idxf = rintf(__fmul_rn(__fadd_rn(x, 10.0f), (float)(255.0 / 10.0)));
        idxf = fminf(fmaxf(idxf, 0.0f), 255.0f);
        float step = __fdiv_rn(10.0f, 255.0f);
        float xs = __fadd_rn(-10.0f, __fmul_rn(idxf, step));
        y = quant_i16(exp_f32(xs), ESCALE);
    }
    if (x >= 0.0f) {                                // line (0,1): only d=0
        float y0 = exp_f32(0.0f), y1 = exp_f32(1.0f);
        float t = __fadd_rn(y0, __fmul_rn(x, __fdiv_rn(__fadd_rn(y1, -y0), 1.0f)));
        y = quant_i16(t, ESCALE);
    }
    if (x > 1.0f) y = quant_i16(exp_f32(1.0f), ESCALE);
    g_exp_lut[i] = y;

    // ---- recip tables (independent of ds) ----
    {
        float step1 = __fdiv_rn((float)(250.0 - 0.1), 255.0f);
        float xs1 = __fadd_rn(0.1f, __fmul_rn((float)i, step1));
        g_rtab1[i] = quant_i16(__fdiv_rn(1.0f, xs1), RSCALE);
        float step2 = __fdiv_rn(250.0f, 255.0f);
        float xs2 = __fadd_rn(250.0f, __fmul_rn((float)i, step2));
        g_rtab2[i] = quant_i16(__fdiv_rn(1.0f, xs2), RSCALE);
    }
}

// piecewise quantized reciprocal of v (dequantized shifted sum)
__device__ __forceinline__ float recip_pw(float v) {
    const float RSCALE = (float)((1.0 / 0.1) * 2.0 / 65535.0);
    float r = quant_i16(__fdiv_rn(1.0f, 0.001f), RSCALE);   // left const
    if (v >= 0.001f) {                                      // line (0.001,0.1)
        float y0 = __fdiv_rn(1.0f, 0.001f), y1 = __fdiv_rn(1.0f, 0.1f);
        float t = __fadd_rn(y0, __fmul_rn(__fadd_rn(v, -0.001f),
                                          __fdiv_rn(__fadd_rn(y1, -y0), (float)(0.1 - 0.001))));
        r = quant_i16(t, RSCALE);
    }
    if (v >= 0.1f) {                                        // table (0.1,250)
        float idxf = rintf(__fmul_rn(__fadd_rn(v, -0.1f), (float)(255.0 / 249.9)));
        idxf = fminf(fmaxf(idxf, 0.0f), 255.0f);
        r = g_rtab1[(int)idxf];
    }
    if (v >= 250.0f) {                                      // table (250,500)
        float idxf = rintf(__fmul_rn(__fadd_rn(v, -250.0f), (float)(255.0 / 250.0)));
        idxf = fminf(fmaxf(idxf, 0.0f), 255.0f);
        r = g_rtab2[(int)idxf];
    }
    if (v >= 500.0f) {                                      // line (500,700)
        float y0 = __fdiv_rn(1.0f, 500.0f), y1 = __fdiv_rn(1.0f, 700.0f);
        float t = __fadd_rn(y0, __fmul_rn(__fadd_rn(v, -500.0f),
                                          __fdiv_rn(__fadd_rn(y1, -y0), 200.0f)));
        r = quant_i16(t, RSCALE);
    }
    if (v > 700.0f) r = quant_i16(__fdiv_rn(1.0f, 700.0f), RSCALE);
    return r;
}

__global__ __launch_bounds__(NTHREADS, 6)
void quant_softmax_kernel(const int* __restrict__ in, float* __restrict__ out) {
    __shared__ float slut32[256 * 32];       // 32x replicated, conflict-free (32 KB)
    __shared__ unsigned smax[NTHREADS];      // packed per-pixel byte maxes
    __shared__ float ssum[4 * NTHREADS];     // [pixel-in-quad][warp*32+lane]

    int tid = threadIdx.x;
    int lane = tid & 31;
    int ce = tid >> 5;                       // channel-eighth 0..7 (16 channels)

    // fill replicated LUT (consecutive -> conflict-free); barrier merged below
#pragma unroll
    for (int i = 0; i < 32; i++) {
        int j = tid + i * NTHREADS;          // 0..8191
        slut32[j] = g_exp_lut[j >> 5];
    }

    int P0 = blockIdx.x * PX_PER_CTA + lane * 4;     // first of 4 pixels
    int b = P0 / HW_DIM;                     // CTA never straddles b (128 | 6400)
    int hw = P0 - b * HW_DIM;

    const int* p = in + (size_t)b * C_DIM * HW_DIM + (size_t)(ce * 16) * HW_DIM + hw;

    // ---- pass 1: 16 int4 loads (4 pixels/channel), pack bytes = pixels ----
    unsigned w[16];
    unsigned mx4 = 0x80808080u;              // per-byte -128
#pragma unroll
    for (int k = 0; k < 16; k++) {
        int4 v = __ldcs((const int4*)&p[k * HW_DIM]);
        unsigned t01 = __byte_perm((unsigned)v.x, (unsigned)v.y, 0x0040);
        unsigned t23 = __byte_perm((unsigned)v.z, (unsigned)v.w, 0x0040);
        unsigned t = __byte_perm(t01, t23, 0x5410);  // [p0,p1,p2,p3] low bytes
        mx4 = __vmaxs4(mx4, t);
        w[k] = t;
    }
    smax[tid] = mx4;
    __syncthreads();                         // covers LUT fill + smax
    unsigned m4 = __vmaxs4(__vmaxs4(smax[lane], smax[lane + 32]),
                           __vmaxs4(smax[lane + 64], smax[lane + 96]));
    m4 = __vmaxs4(m4, __vmaxs4(__vmaxs4(smax[lane + 128], smax[lane + 160]),
                               __vmaxs4(smax[lane + 192], smax[lane + 224])));

    // ---- pass 2: d = (m-q) mod 256 per byte, conflict-free LUT, 4 sums ----
    float s0 = 0.0f, s1 = 0.0f, s2 = 0.0f, s3 = 0.0f;
#pragma unroll
    for (int k = 0; k < 16; k++) {
        unsigned d4 = __vsub4(m4, w[k]);     // exact: d in [0,255]
        s0 += slut32[(d4 & 0xFF) * 32 + lane];
        s1 += slut32[((d4 >> 8) & 0xFF) * 32 + lane];
        s2 += slut32[((d4 >> 16) & 0xFF) * 32 + lane];
        s3 += slut32[(d4 >> 24) * 32 + lane];
    }
    ssum[0 * NTHREADS + ce * 32 + lane] = s0;
    ssum[1 * NTHREADS + ce * 32 + lane] = s1;
    ssum[2 * NTHREADS + ce * 32 + lane] = s2;
    ssum[3 * NTHREADS + ce * 32 + lane] = s3;
    __syncthreads();

    // ---- per-pixel reciprocal (4 per thread) ----
    const float DIVSC = (float)(2.0 / 65535.0 * 128.0);
    float r[4];
#pragma unroll
    for (int j = 0; j < 4; j++) {
        float sum = 0.0f;
#pragma unroll
        for (int wq = 0; wq < 8; wq++)
            sum += ssum[j * NTHREADS + wq * 32 + lane];     // integers: exact
        float sum_sh = rintf(sum * 0.0078125f);             // exact /128 (shift=7)
        sum_sh = fminf(fmaxf(sum_sh, -32768.0f), 32767.0f);
        r[j] = recip_pw(__fmul_rn(sum_sh, DIVSC));
    }

    // ---- pass 3: second LUT pass, out = clip(round((e*r)*K), i8)*OUT_SCALE ----
    const float KF = (float)((2.0 / 65535.0) * ((1.0 / 0.1) * 2.0 / 65535.0) / (2.0 / 255.0));
    const float OUTSC = (float)(2.0 / 255.0);
    float* po = out + (size_t)b * C_DIM * HW_DIM + (size_t)(ce * 16) * HW_DIM + hw;
#pragma unroll
    for (int k = 0; k < 16; k++) {
        unsigned d4 = __vsub4(m4, w[k]);
        float e0 = slut32[(d4 & 0xFF) * 32 + lane];
        float e1 = slut32[((d4 >> 8) & 0xFF) * 32 + lane];
        float e2 = slut32[((d4 >> 16) & 0xFF) * 32 + lane];
        float e3 = slut32[(d4 >> 24) * 32 + lane];
        float p0 = rintf(__fmul_rn(__fmul_rn(e0, r[0]), KF));
        float p1 = rintf(__fmul_rn(__fmul_rn(e1, r[1]), KF));
        float p2 = rintf(__fmul_rn(__fmul_rn(e2, r[2]), KF));
        float p3 = rintf(__fmul_rn(__fmul_rn(e3, r[3]), KF));
        p0 = fminf(fmaxf(p0, -128.0f), 127.0f) * OUTSC;
        p1 = fminf(fmaxf(p1, -128.0f), 127.0f) * OUTSC;
        p2 = fminf(fmaxf(p2, -128.0f), 127.0f) * OUTSC;
        p3 = fminf(fmaxf(p3, -128.0f), 127.0f) * OUTSC;
        float4 o = make_float4(p0, p1, p2, p3);
        __stcs((float4*)&po[k * HW_DIM], o);
    }
}

extern "C" void kernel_launch(void* const* d_in, const int* in_sizes, int n_in,
                              void* d_out, int out_size) {
    const int* data = (const int*)d_in[0];
    const float* data_scale = (const float*)d_in[1];
    float* out = (float*)d_out;

    build_luts_kernel<<<1, 256>>>(data_scale);

    int total = in_sizes[0];
    int B = total / (C_DIM * HW_DIM);
    int blocks = (B * HW_DIM) / PX_PER_CTA;
    quant_softmax_kernel<<<blocks, NTHREADS>>>(data, out);
}

// round 10
// speedup vs baseline: 1.7530x; 1.7530x over previous
#include <cuda_runtime.h>
#include <math.h>
#include <stdint.h>

// ---------------------------------------------------------------------------
// QuantSoftmax: B=32, C=128, H=W=80 (HW=6400). int32 input (int8 repr, zp=0),
// float32 output. Piecewise-quantized exp (qint16) + reciprocal (qint16),
// requantized to int8*OUT_SCALE.
//
// xd = -(qmax - q)*ds takes only 256 values -> exp collapses to a 256-entry
// LUT. SINGLE kernel: each CTA builds the LUT into shared memory itself
// (expf-based, 2 entries/thread, amortized over 8192 elements/CTA) — no
// prologue kernel, no global tables. Reciprocal piecewise is computed
// arithmetically per pixel (table entry == quant(1/xs) at the snapped grid
// point; IEEE fdiv is deterministic).
// Main structure = best-known R5: 64 pixels/CTA, 128 threads, 2 thr/pixel,
// 16KB in-place smem staging (q bytes -> exp_q u16), 12 CTAs/SM.
// ---------------------------------------------------------------------------

#define C_DIM 128
#define HW_DIM 6400
#define PX 64          // pixels per block
#define NTHREADS 128   // 2 threads per pixel
#define KITER 16       // 64 channels / 4 per u32

__device__ __forceinline__ float quant_i16(float y, float scale) {
    float q = rintf(__fdiv_rn(y, scale));           // jnp.round = half-even
    return fminf(fmaxf(q, -32768.0f), 32767.0f);
}

// build one exp-LUT entry: d = qmax - q in [0,255], x = -d*ds
__device__ __forceinline__ float exp_lut_entry(int i, float ds) {
    const float ESCALE = (float)(2.0 / 65535.0);
    float x = __fmul_rn(-(float)i, ds);
    float y = quant_i16(expf(-40.0f), ESCALE);      // left constant
    if (x >= -40.0f) {                              // line (-40,-20)
        float y0 = expf(-40.0f), y1 = expf(-20.0f);
        float t = __fadd_rn(y0, __fmul_rn(__fadd_rn(x, 40.0f),
                                          __fdiv_rn(__fadd_rn(y1, -y0), 20.0f)));
        y = quant_i16(t, ESCALE);
    }
    if (x >= -20.0f) {                              // table (-20,-10)
        float idxf = rintf(__fmul_rn(__fadd_rn(x, 20.0f), (float)(255.0 / 10.0)));
        idxf = fminf(fmaxf(idxf, 0.0f), 255.0f);
        float step = __fdiv_rn(10.0f, 255.0f);
        float xs = __fadd_rn(-20.0f, __fmul_rn(idxf, step));
        y = quant_i16(expf(xs), ESCALE);
    }
    if (x >= -10.0f) {                              // table (-10,0)
        float idxf = rintf(__fmul_rn(__fadd_rn(x, 10.0f), (float)(255.0 / 10.0)));
        idxf = fminf(fmaxf(idxf, 0.0f), 255.0f);
        float step = __fdiv_rn(10.0f, 255.0f);
        float xs = __fadd_rn(-10.0f, __fmul_rn(idxf, step));
        y = quant_i16(expf(xs), ESCALE);
    }
    if (x >= 0.0f) {                                // line (0,1): only d=0
        float y0 = expf(0.0f), y1 = expf(1.0f);
        float t = __fadd_rn(y0, __fmul_rn(x, __fdiv_rn(__fadd_rn(y1, -y0), 1.0f)));
        y = quant_i16(t, ESCALE);
    }
    if (x > 1.0f) y = quant_i16(expf(1.0f), ESCALE);
    return y;
}

__global__ __launch_bounds__(NTHREADS, 12)
void quant_softmax_kernel(const int* __restrict__ in, float* __restrict__ out,
                          const float* __restrict__ ds_ptr) {
    // In-place union buffer, 16 KB:
    //   pass 1: slot (h*32 + 2k)*64 + px  <- 4 byte-packed q values
    //   pass 2: slots (h*32+2k)/(h*32+2k+1) <- u16x2 exp_q for those 4 channels
    __shared__ uint32_t buf[64 * PX];
    __shared__ float slut[256];
    __shared__ int smax[NTHREADS];
    __shared__ float ssum[NTHREADS];

    int tid = threadIdx.x;
    float ds = __ldg(ds_ptr);
    slut[tid] = exp_lut_entry(tid, ds);
    slut[tid + 128] = exp_lut_entry(tid + 128, ds);

    int h = tid >> 6;                  // half: channels [h*64, h*64+64)
    int px = tid & 63;                 // pixel within tile

    int tile = blockIdx.x;             // b * 100 + t
    int b = tile / (HW_DIM / PX);
    int hw = (tile % (HW_DIM / PX)) * PX + px;

    const int* p = in + (size_t)b * C_DIM * HW_DIM + (size_t)(h * 64) * HW_DIM + hw;

    // ---- pass 1: load own 64 channels, byte-pack, partial max ----
    unsigned mx4 = 0x80808080u;        // all lanes = -128
#pragma unroll
    for (int k = 0; k < KITER; k++) {
        int q0 = __ldcs(&p[(4 * k + 0) * HW_DIM]);
        int q1 = __ldcs(&p[(4 * k + 1) * HW_DIM]);
        int q2 = __ldcs(&p[(4 * k + 2) * HW_DIM]);
        int q3 = __ldcs(&p[(4 * k + 3) * HW_DIM]);
        unsigned w = (unsigned)(q0 & 0xFF) | ((unsigned)(q1 & 0xFF) << 8) |
                     ((unsigned)(q2 & 0xFF) << 16) | ((unsigned)q3 << 24);
        mx4 = __vmaxs4(mx4, w);
        buf[(h * 32 + 2 * k) * PX + px] = w;
    }
    int mp = (int)(signed char)(mx4 & 0xFF);
    mp = max(mp, (int)(signed char)((mx4 >> 8) & 0xFF));
    mp = max(mp, (int)(signed char)((mx4 >> 16) & 0xFF));
    mp = max(mp, (int)(signed char)(mx4 >> 24));
    smax[tid] = mp;
    __syncthreads();                   // covers LUT build + smax + buf
    int m = max(smax[px], smax[px + 64]);

    // ---- pass 2: exp LUT (one lookup/elem), partial sum, overwrite in place ----
    float sum = 0.0f;
#pragma unroll
    for (int k = 0; k < KITER; k++) {
        unsigned w = buf[(h * 32 + 2 * k) * PX + px];
        int d0 = m - (int)(signed char)(w & 0xFF);
        int d1 = m - (int)(signed char)((w >> 8) & 0xFF);
        int d2 = m - (int)(signed char)((w >> 16) & 0xFF);
        int d3 = m - (int)(signed char)(w >> 24);
        float e0 = slut[d0], e1 = slut[d1], e2 = slut[d2], e3 = slut[d3];
        sum += (e0 + e1) + (e2 + e3);  // integers < 2^22: exact
        buf[(h * 32 + 2 * k + 0) * PX + px] = (uint32_t)(int)e0 | (((uint32_t)(int)e1) << 16);
        buf[(h * 32 + 2 * k + 1) * PX + px] = (uint32_t)(int)e2 | (((uint32_t)(int)e3) << 16);
    }
    ssum[tid] = sum;
    __syncthreads();
    sum = ssum[px] + ssum[px + 64];    // both integer-valued, exact

    // ---- reciprocal (both half-threads compute identically) ----
    // shift = ceil(log2(128)) = 7
    float sum_sh = rintf(sum * 0.0078125f);                 // exact /128
    sum_sh = fminf(fmaxf(sum_sh, -32768.0f), 32767.0f);
    const float DIVSC = (float)(2.0 / 65535.0 * 128.0);
    float v = __fmul_rn(sum_sh, DIVSC);
    const float RSCALE = (float)((1.0 / 0.1) * 2.0 / 65535.0);

    float r = quant_i16(__fdiv_rn(1.0f, 0.001f), RSCALE);   // left const
    if (v >= 0.001f) {                                      // line (0.001,0.1)
        float y0 = __fdiv_rn(1.0f, 0.001f), y1 = __fdiv_rn(1.0f, 0.1f);
        float t = __fadd_rn(y0, __fmul_rn(__fadd_rn(v, -0.001f),
                                          __fdiv_rn(__fadd_rn(y1, -y0), (float)(0.1 - 0.001))));
        r = quant_i16(t, RSCALE);
    }
    if (v >= 0.1f) {                                        // table (0.1,250): compute entry
        float idxf = rintf(__fmul_rn(__fadd_rn(v, -0.1f), (float)(255.0 / 249.9)));
        idxf = fminf(fmaxf(idxf, 0.0f), 255.0f);
        float step1 = __fdiv_rn((float)(250.0 - 0.1), 255.0f);
        float xs = __fadd_rn(0.1f, __fmul_rn(idxf, step1));
        r = quant_i16(__fdiv_rn(1.0f, xs), RSCALE);
    }
    if (v >= 250.0f) {                                      // table (250,500): compute entry
        float idxf = rintf(__fmul_rn(__fadd_rn(v, -250.0f), (float)(255.0 / 250.0)));
        idxf = fminf(fmaxf(idxf, 0.0f), 255.0f);
        float step2 = __fdiv_rn(250.0f, 255.0f);
        float xs = __fadd_rn(250.0f, __fmul_rn(idxf, step2));
        r = quant_i16(__fdiv_rn(1.0f, xs), RSCALE);
    }
    if (v >= 500.0f) {                                      // line (500,700)
        float y0 = __fdiv_rn(1.0f, 500.0f), y1 = __fdiv_rn(1.0f, 700.0f);
        float t = __fadd_rn(y0, __fmul_rn(__fadd_rn(v, -500.0f),
                                          __fdiv_rn(__fadd_rn(y1, -y0), 200.0f)));
        r = quant_i16(t, RSCALE);
    }
    if (v > 700.0f) r = quant_i16(__fdiv_rn(1.0f, 700.0f), RSCALE);

    // ---- pass 3: out = clip(round((exp_q*recip_q)*K), i8) * OUT_SCALE ----
    const float KF = (float)((2.0 / 65535.0) * ((1.0 / 0.1) * 2.0 / 65535.0) / (2.0 / 255.0));
    const float OUTSC = (float)(2.0 / 255.0);
    float* po = out + (size_t)b * C_DIM * HW_DIM + (size_t)(h * 64) * HW_DIM + hw;
#pragma unroll
    for (int k = 0; k < KITER; k++) {
        unsigned w0 = buf[(h * 32 + 2 * k + 0) * PX + px];
        unsigned w1 = buf[(h * 32 + 2 * k + 1) * PX + px];
        float e0 = (float)(w0 & 0xFFFF);
        float e1 = (float)(w0 >> 16);
        float e2 = (float)(w1 & 0xFFFF);
        float e3 = (float)(w1 >> 16);
        float p0 = rintf(__fmul_rn(__fmul_rn(e0, r), KF));
        float p1 = rintf(__fmul_rn(__fmul_rn(e1, r), KF));
        float p2 = rintf(__fmul_rn(__fmul_rn(e2, r), KF));
        float p3 = rintf(__fmul_rn(__fmul_rn(e3, r), KF));
        p0 = fminf(fmaxf(p0, -128.0f), 127.0f);
        p1 = fminf(fmaxf(p1, -128.0f), 127.0f);
        p2 = fminf(fmaxf(p2, -128.0f), 127.0f);
        p3 = fminf(fmaxf(p3, -128.0f), 127.0f);
        __stcs(&po[(4 * k + 0) * HW_DIM], p0 * OUTSC);
        __stcs(&po[(4 * k + 1) * HW_DIM], p1 * OUTSC);
        __stcs(&po[(4 * k + 2) * HW_DIM], p2 * OUTSC);
        __stcs(&po[(4 * k + 3) * HW_DIM], p3 * OUTSC);
    }
}

extern "C" void kernel_launch(void* const* d_in, const int* in_sizes, int n_in,
                              void* d_out, int out_size) {
    const int* data = (const int*)d_in[0];
    const float* data_scale = (const float*)d_in[1];
    float* out = (float*)d_out;

    int total = in_sizes[0];
    int B = total / (C_DIM * HW_DIM);
    int blocks = B * (HW_DIM / PX);
    quant_softmax_kernel<<<blocks, NTHREADS>>>(data, out, data_scale);
}

// round 11
// speedup vs baseline: 1.7715x; 1.0106x over previous
#include <cuda_runtime.h>
#include <math.h>
#include <stdint.h>

// ---------------------------------------------------------------------------
// QuantSoftmax: B=32, C=128, H=W=80 (HW=6400). int32 input (int8 repr, zp=0),
// float32 output. Piecewise-quantized exp (qint16) + reciprocal (qint16),
// requantized to int8*OUT_SCALE.
//
// exp collapses to a 256-entry LUT over d = qmax-q; each CTA builds it in
// smem (expf, 2 entries/thread). Single kernel. Structure (best-known):
// 64 pixels/CTA, 128 threads, 2 threads/pixel, 16KB in-place smem staging
// (q bytes -> exp_q u16), 12 CTAs/SM.
// This revision: byte-SIMD peepholes (PRMT pack/extract, VSUB4 for d),
// integer LUT + integer channel-sum (exact, < 2^22), loads issued before
// the MUFU-heavy LUT build.
// ---------------------------------------------------------------------------

#define C_DIM 128
#define HW_DIM 6400
#define PX 64          // pixels per block
#define NTHREADS 128   // 2 threads per pixel
#define KITER 16       // 64 channels / 4 per u32

__device__ __forceinline__ float quant_i16(float y, float scale) {
    float q = rintf(__fdiv_rn(y, scale));           // jnp.round = half-even
    return fminf(fmaxf(q, -32768.0f), 32767.0f);
}

// build one exp-LUT entry: d = qmax - q in [0,255], x = -d*ds
__device__ __forceinline__ float exp_lut_entry(int i, float ds) {
    const float ESCALE = (float)(2.0 / 65535.0);
    float x = __fmul_rn(-(float)i, ds);
    float y = quant_i16(expf(-40.0f), ESCALE);      // left constant
    if (x >= -40.0f) {                              // line (-40,-20)
        float y0 = expf(-40.0f), y1 = expf(-20.0f);
        float t = __fadd_rn(y0, __fmul_rn(__fadd_rn(x, 40.0f),
                                          __fdiv_rn(__fadd_rn(y1, -y0), 20.0f)));
        y = quant_i16(t, ESCALE);
    }
    if (x >= -20.0f) {                              // table (-20,-10)
        float idxf = rintf(__fmul_rn(__fadd_rn(x, 20.0f), (float)(255.0 / 10.0)));
        idxf = fminf(fmaxf(idxf, 0.0f), 255.0f);
        float step = __fdiv_rn(10.0f, 255.0f);
        float xs = __fadd_rn(-20.0f, __fmul_rn(idxf, step));
        y = quant_i16(expf(xs), ESCALE);
    }
    if (x >= -10.0f) {                              // table (-10,0)
        float idxf = rintf(__fmul_rn(__fadd_rn(x, 10.0f), (float)(255.0 / 10.0)));
        idxf = fminf(fmaxf(idxf, 0.0f), 255.0f);
        float step = __fdiv_rn(10.0f, 255.0f);
        float xs = __fadd_rn(-10.0f, __fmul_rn(idxf, step));
        y = quant_i16(expf(xs), ESCALE);
    }
    if (x >= 0.0f) {                                // line (0,1): only d=0
        float y0 = expf(0.0f), y1 = expf(1.0f);
        float t = __fadd_rn(y0, __fmul_rn(x, __fdiv_rn(__fadd_rn(y1, -y0), 1.0f)));
        y = quant_i16(t, ESCALE);
    }
    if (x > 1.0f) y = quant_i16(expf(1.0f), ESCALE);
    return y;
}

__global__ __launch_bounds__(NTHREADS, 12)
void quant_softmax_kernel(const int* __restrict__ in, float* __restrict__ out,
                          const float* __restrict__ ds_ptr) {
    // In-place union buffer, 16 KB:
    //   pass 1: slot (h*32 + 2k)*64 + px  <- 4 byte-packed q values
    //   pass 2: slots (h*32+2k)/(h*32+2k+1) <- u16x2 exp_q for those 4 channels
    __shared__ uint32_t buf[64 * PX];
    __shared__ unsigned slut_i[256];   // exp_q as u32 integer
    __shared__ int smax[NTHREADS];
    __shared__ int ssum[NTHREADS];

    int tid = threadIdx.x;
    int h = tid >> 6;                  // half: channels [h*64, h*64+64)
    int px = tid & 63;                 // pixel within tile

    int tile = blockIdx.x;             // b * 100 + t
    int b = tile / (HW_DIM / PX);
    int hw = (tile % (HW_DIM / PX)) * PX + px;

    const int* p = in + (size_t)b * C_DIM * HW_DIM + (size_t)(h * 64) * HW_DIM + hw;

    // ---- pass 1 FIRST (loads in flight while LUT is built below) ----
    unsigned mx4 = 0x80808080u;        // all lanes = -128
#pragma unroll
    for (int k = 0; k < KITER; k++) {
        int q0 = __ldcs(&p[(4 * k + 0) * HW_DIM]);
        int q1 = __ldcs(&p[(4 * k + 1) * HW_DIM]);
        int q2 = __ldcs(&p[(4 * k + 2) * HW_DIM]);
        int q3 = __ldcs(&p[(4 * k + 3) * HW_DIM]);
        unsigned t01 = __byte_perm((unsigned)q0, (unsigned)q1, 0x0040);
        unsigned t23 = __byte_perm((unsigned)q2, (unsigned)q3, 0x0040);
        unsigned w = __byte_perm(t01, t23, 0x5410);   // [q0,q1,q2,q3] low bytes
        mx4 = __vmaxs4(mx4, w);
        buf[(h * 32 + 2 * k) * PX + px] = w;
    }
    int mp = (int)(signed char)(mx4 & 0xFF);
    mp = max(mp, (int)(signed char)((mx4 >> 8) & 0xFF));
    mp = max(mp, (int)(signed char)((mx4 >> 16) & 0xFF));
    mp = max(mp, (int)(signed char)(mx4 >> 24));
    smax[tid] = mp;

    // ---- LUT build (overlaps outstanding loads of other warps) ----
    float ds = __ldg(ds_ptr);
    slut_i[tid] = (unsigned)(int)exp_lut_entry(tid, ds);
    slut_i[tid + 128] = (unsigned)(int)exp_lut_entry(tid + 128, ds);
    __syncthreads();                   // covers buf + smax + slut_i

    int m = max(smax[px], smax[px + 64]);
    unsigned m4 = (unsigned)(m & 0xFF) * 0x01010101u;   // broadcast max byte

    // ---- pass 2: d via VSUB4, integer LUT, integer sum; pack exp_q back ----
    int sa = 0, sb = 0;
#pragma unroll
    for (int k = 0; k < KITER; k++) {
        unsigned w = buf[(h * 32 + 2 * k) * PX + px];
        unsigned d4 = __vsub4(m4, w);                   // per-byte (m-q) mod 256 = d
        int a0 = (int)__byte_perm(d4, 0, 0x4440);
        int a1 = (int)__byte_perm(d4, 0, 0x4441);
        int a2 = (int)__byte_perm(d4, 0, 0x4442);
        int a3 = (int)__byte_perm(d4, 0, 0x4443);
        unsigned e0 = slut_i[a0];
        unsigned e1 = slut_i[a1];
        unsigned e2 = slut_i[a2];
        unsigned e3 = slut_i[a3];
        sa += (int)(e0 + e1);
        sb += (int)(e2 + e3);                           // total < 2^22: exact
        buf[(h * 32 + 2 * k + 0) * PX + px] = __byte_perm(e0, e1, 0x5410);
        buf[(h * 32 + 2 * k + 1) * PX + px] = __byte_perm(e2, e3, 0x5410);
    }
    ssum[tid] = sa + sb;
    __syncthreads();
    float sum = (float)(ssum[px] + ssum[px + 64]);      // exact I2F (< 2^22)

    // ---- reciprocal (both half-threads compute identically) ----
    // shift = ceil(log2(128)) = 7
    float sum_sh = rintf(sum * 0.0078125f);                 // exact /128
    sum_sh = fminf(fmaxf(sum_sh, -32768.0f), 32767.0f);
    const float DIVSC = (float)(2.0 / 65535.0 * 128.0);
    float v = __fmul_rn(sum_sh, DIVSC);
    const float RSCALE = (float)((1.0 / 0.1) * 2.0 / 65535.0);

    float r = quant_i16(__fdiv_rn(1.0f, 0.001f), RSCALE);   // left const
    if (v >= 0.001f) {                                      // line (0.001,0.1)
        float y0 = __fdiv_rn(1.0f, 0.001f), y1 = __fdiv_rn(1.0f, 0.1f);
        float t = __fadd_rn(y0, __fmul_rn(__fadd_rn(v, -0.001f),
                                          __fdiv_rn(__fadd_rn(y1, -y0), (float)(0.1 - 0.001))));
        r = quant_i16(t, RSCALE);
    }
    if (v >= 0.1f) {                                        // table (0.1,250): compute entry
        float idxf = rintf(__fmul_rn(__fadd_rn(v, -0.1f), (float)(255.0 / 249.9)));
        idxf = fminf(fmaxf(idxf, 0.0f), 255.0f);
        float step1 = __fdiv_rn((float)(250.0 - 0.1), 255.0f);
        float xs = __fadd_rn(0.1f, __fmul_rn(idxf, step1));
        r = quant_i16(__fdiv_rn(1.0f, xs), RSCALE);
    }
    if (v >= 250.0f) {                                      // table (250,500): compute entry
        float idxf = rintf(__fmul_rn(__fadd_rn(v, -250.0f), (float)(255.0 / 250.0)));
        idxf = fminf(fmaxf(idxf, 0.0f), 255.0f);
        float step2 = __fdiv_rn(250.0f, 255.0f);
        float xs = __fadd_rn(250.0f, __fmul_rn(idxf, step2));
        r = quant_i16(__fdiv_rn(1.0f, xs), RSCALE);
    }
    if (v >= 500.0f) {                                      // line (500,700)
        float y0 = __fdiv_rn(1.0f, 500.0f), y1 = __fdiv_rn(1.0f, 700.0f);
        float t = __fadd_rn(y0, __fmul_rn(__fadd_rn(v, -500.0f),
                                          __fdiv_rn(__fadd_rn(y1, -y0), 200.0f)));
        r = quant_i16(t, RSCALE);
    }
    if (v > 700.0f) r = quant_i16(__fdiv_rn(1.0f, 700.0f), RSCALE);

    // ---- pass 3: out = clip(round((exp_q*recip_q)*K), i8) * OUT_SCALE ----
    const float KF = (float)((2.0 / 65535.0) * ((1.0 / 0.1) * 2.0 / 65535.0) / (2.0 / 255.0));
    const float OUTSC = (float)(2.0 / 255.0);
    float* po = out + (size_t)b * C_DIM * HW_DIM + (size_t)(h * 64) * HW_DIM + hw;
#pragma unroll
    for (int k = 0; k < KITER; k++) {
        unsigned w0 = buf[(h * 32 + 2 * k + 0) * PX + px];
        unsigned w1 = buf[(h * 32 + 2 * k + 1) * PX + px];
        float e0 = (float)(int)__byte_perm(w0, 0, 0x4410);  // w0 & 0xFFFF
        float e1 = (float)(w0 >> 16);
        float e2 = (float)(int)__byte_perm(w1, 0, 0x4410);
        float e3 = (float)(w1 >> 16);
        float p0 = rintf(__fmul_rn(__fmul_rn(e0, r), KF));
        float p1 = rintf(__fmul_rn(__fmul_rn(e1, r), KF));
        float p2 = rintf(__fmul_rn(__fmul_rn(e2, r), KF));
        float p3 = rintf(__fmul_rn(__fmul_rn(e3, r), KF));
        p0 = fminf(fmaxf(p0, -128.0f), 127.0f);
        p1 = fminf(fmaxf(p1, -128.0f), 127.0f);
        p2 = fminf(fmaxf(p2, -128.0f), 127.0f);
        p3 = fminf(fmaxf(p3, -128.0f), 127.0f);
        __stcs(&po[(4 * k + 0) * HW_DIM], p0 * OUTSC);
        __stcs(&po[(4 * k + 1) * HW_DIM], p1 * OUTSC);
        __stcs(&po[(4 * k + 2) * HW_DIM], p2 * OUTSC);
        __stcs(&po[(4 * k + 3) * HW_DIM], p3 * OUTSC);
    }
}

extern "C" void kernel_launch(void* const* d_in, const int* in_sizes, int n_in,
                              void* d_out, int out_size) {
    const int* data = (const int*)d_in[0];
    const float* data_scale = (const float*)d_in[1];
    float* out = (float*)d_out;

    int total = in_sizes[0];
    int B = total / (C_DIM * HW_DIM);
    int blocks = B * (HW_DIM / PX);
    quant_softmax_kernel<<<blocks, NTHREADS>>>(data, out, data_scale);
}